// round 14
// baseline (speedup 1.0000x reference)
#include <cuda_runtime.h>
#include <cuda_bf16.h>
#include <math.h>
#include <stdint.h>

#define H    300
#define G3   900
#define NB   2048
#define SEGL 48
#define NW   1800
#define KP   320   // K padded: 10 chunks of 32

#define A_STRIDE 40
#define B_STRIDE 40
#define SMEM_X 97280    // xproj layout (unchanged from R13)

// gru_persist SMEM layout:
//  A bufs: [2buf][2hl][32 krows][144B] at 0 .. 18432   (buf stride 9216, hl stride 4608)
//  B buf0: 18432 .. 56832  ([2hl][240][40] bf16 = 38400B)
//  B buf1: 61824 .. 100224 (disjoint from Gs overlay)
//  Gs (stage): overlay [0, 61696)
#define GRU_AB0   18432
#define GRU_AB1   61824
#define SMEM_GRU  100224

// ---------------- device scratch (zero-initialized at module load) ----------------
__device__ float g_xpt[(size_t)2 * SEGL * G3 * NB];                // [d][l][n=g*300+hc][m]
__device__ __nv_bfloat16 g_hT[(size_t)2 * 2 * 2 * KP * NB];        // [d][pp][hl][k][m]
__device__ __nv_bfloat16 g_wpk[(size_t)2 * 4 * 2 * 10 * 7680];     // W_hh slabs
__device__ __nv_bfloat16 g_wih_pk[(size_t)8 * 2 * 10 * 7680];      // W_ih slabs (N padded 1920)
__device__ unsigned g_gcnt[64 * 32];                               // group barriers (128B slots)
__device__ unsigned g_gph[64 * 32];

__device__ __forceinline__ __nv_bfloat16* HT(int d, int pp, int hl) {
    return g_hT + ((size_t)((d * 2 + pp) * 2 + hl)) * KP * NB;
}
__device__ __forceinline__ float sigmoidf(float v) { return 1.0f / (1.0f + expf(-v)); }

__device__ __forceinline__ void mma16816(float* c, const uint32_t* a, uint32_t b0, uint32_t b1) {
    asm volatile("mma.sync.aligned.m16n8k16.row.col.f32.bf16.bf16.f32 "
        "{%0,%1,%2,%3}, {%4,%5,%6,%7}, {%8,%9}, {%0,%1,%2,%3};"
        : "+f"(c[0]), "+f"(c[1]), "+f"(c[2]), "+f"(c[3])
        : "r"(a[0]), "r"(a[1]), "r"(a[2]), "r"(a[3]), "r"(b0), "r"(b1));
}
__device__ __forceinline__ void ldsm4(uint32_t& a, uint32_t& b, uint32_t& c, uint32_t& d, uint32_t addr) {
    asm volatile("ldmatrix.sync.aligned.m8n8.x4.shared.b16 {%0,%1,%2,%3}, [%4];"
        : "=r"(a), "=r"(b), "=r"(c), "=r"(d) : "r"(addr));
}
__device__ __forceinline__ void ldsm4t(uint32_t& a, uint32_t& b, uint32_t& c, uint32_t& d, uint32_t addr) {
    asm volatile("ldmatrix.sync.aligned.m8n8.x4.trans.shared.b16 {%0,%1,%2,%3}, [%4];"
        : "=r"(a), "=r"(b), "=r"(c), "=r"(d) : "r"(addr));
}
__device__ __forceinline__ void cpa16(uint32_t dst, const void* src) {
    asm volatile("cp.async.cg.shared.global [%0], [%1], 16;" :: "r"(dst), "l"(src));
}
#define CP_COMMIT() asm volatile("cp.async.commit_group;")
#define CP_WAIT1()  asm volatile("cp.async.wait_group 1;")
#define CP_WAIT0()  asm volatile("cp.async.wait_group 0;")

// ---------------- setup: h0 = segment max -> hT hi/lo (k-major) ----------------
__global__ void setup_h0(const float* __restrict__ x) {
    int b = blockIdx.x;
    const float* xb = x + (size_t)b * SEGL * H;
    for (int h = threadIdx.x; h < H; h += blockDim.x) {
        float mx = -INFINITY;
        #pragma unroll 4
        for (int l = 0; l < SEGL; l++) mx = fmaxf(mx, xb[(size_t)l * H + h]);
        __nv_bfloat16 hi = __float2bfloat16(mx);
        __nv_bfloat16 lo = __float2bfloat16(mx - __bfloat162float(hi));
        for (int d = 0; d < 2; d++) {
            HT(d, 0, 0)[(size_t)h * NB + b] = hi;
            HT(d, 0, 1)[(size_t)h * NB + b] = lo;
        }
    }
}

// ---------------- prep: W_hh -> gate-blocked hi/lo k32 slabs ----------------
__global__ void prep_whh(const float* __restrict__ whf, const float* __restrict__ whb) {
    int c = blockIdx.x, nt = blockIdx.y, d = blockIdx.z;
    const float* w = d ? whb : whf;
    __nv_bfloat16* hi_base = g_wpk + (size_t)(((d * 4 + nt) * 2 + 0) * 10 + c) * 7680;
    __nv_bfloat16* lo_base = g_wpk + (size_t)(((d * 4 + nt) * 2 + 1) * 10 + c) * 7680;
    for (int e = threadIdx.x; e < 7680; e += blockDim.x) {
        int row = e >> 5, col = e & 31;
        int g = row / 80, hcl = row % 80;
        int hc = nt * 80 + hcl;
        int k = c * 32 + col;
        float v = (hc < H && k < H) ? w[(size_t)(g * H + hc) * H + k] : 0.0f;
        __nv_bfloat16 hi = __float2bfloat16(v);
        __nv_bfloat16 lo = __float2bfloat16(v - __bfloat162float(hi));
        hi_base[e] = hi;
        lo_base[e] = lo;
    }
}

// ---------------- prep: W_ih -> hi/lo k32 slabs, N padded to 1920 ----------------
__global__ void prep_wih(const float* __restrict__ wif, const float* __restrict__ wib) {
    int c = blockIdx.x, nt = blockIdx.y;
    __nv_bfloat16* hi_base = g_wih_pk + (size_t)((nt * 2 + 0) * 10 + c) * 7680;
    __nv_bfloat16* lo_base = g_wih_pk + (size_t)((nt * 2 + 1) * 10 + c) * 7680;
    for (int e = threadIdx.x; e < 7680; e += blockDim.x) {
        int row = e >> 5, col = e & 31;
        int n = nt * 240 + row;
        int k = c * 32 + col;
        float v = 0.0f;
        if (k < H) {
            if (n < G3)      v = wif[(size_t)n * H + k];
            else if (n < NW) v = wib[(size_t)(n - G3) * H + k];
        }
        __nv_bfloat16 hi = __float2bfloat16(v);
        __nv_bfloat16 lo = __float2bfloat16(v - __bfloat162float(hi));
        hi_base[e] = hi;
        lo_base[e] = lo;
    }
}

// ---------------- xproj MMA (unchanged from R13) ----------------
__global__ __launch_bounds__(256, 2) void xproj_mma(
        const float* __restrict__ x, const float* __restrict__ bias,
        const float* __restrict__ bif, const float* __restrict__ bib) {
    extern __shared__ char smraw[];
    __nv_bfloat16* As = (__nv_bfloat16*)smraw;
    __nv_bfloat16* Bs = (__nv_bfloat16*)(smraw + 20480);
    float* Gs = (float*)smraw;
    uint32_t sBu = (uint32_t)__cvta_generic_to_shared(Bs);

    const int nt = blockIdx.x, mt = blockIdx.y, l = blockIdx.z;
    const int b0 = mt * 64;
    const int tid = threadIdx.x;
    const int wid = tid >> 5, lane = tid & 31;
    const int wm = wid >> 1, wn = wid & 1;
    const int grp = lane >> 2, tig = lane & 3;

    const __nv_bfloat16* wslab = g_wih_pk + (size_t)(nt * 2) * 10 * 7680;

    const int arow = tid >> 2, agrp = tid & 3;
    const size_t xbase = ((size_t)(b0 + arow) * SEGL + l) * H;
    float4 xv0, xv1;

    auto loadX = [&](int c) {
        int k = c * 32 + agrp * 8;
        xv0 = make_float4(0.f, 0.f, 0.f, 0.f);
        xv1 = make_float4(0.f, 0.f, 0.f, 0.f);
        if (k < H) {
            float4 v = *(const float4*)(x + xbase + k);
            float4 bv = *(const float4*)(bias + k);
            xv0 = make_float4(fmaxf(v.x + bv.x, 0.f), fmaxf(v.y + bv.y, 0.f),
                              fmaxf(v.z + bv.z, 0.f), fmaxf(v.w + bv.w, 0.f));
        }
        if (k + 4 < H) {
            float4 v = *(const float4*)(x + xbase + k + 4);
            float4 bv = *(const float4*)(bias + k + 4);
            xv1 = make_float4(fmaxf(v.x + bv.x, 0.f), fmaxf(v.y + bv.y, 0.f),
                              fmaxf(v.z + bv.z, 0.f), fmaxf(v.w + bv.w, 0.f));
        }
    };
    auto writeA = [&](int buf) {
        float vv[8] = {xv0.x, xv0.y, xv0.z, xv0.w, xv1.x, xv1.y, xv1.z, xv1.w};
        union { __nv_bfloat16 h[8]; uint4 u; } ph, pl;
        #pragma unroll
        for (int i = 0; i < 8; i++) {
            __nv_bfloat16 hi = __float2bfloat16(vv[i]);
            ph.h[i] = hi;
            pl.h[i] = __float2bfloat16(vv[i] - __bfloat162float(hi));
        }
        *(uint4*)&As[((buf * 2 + 0) * 64 + arow) * A_STRIDE + agrp * 8] = ph.u;
        *(uint4*)&As[((buf * 2 + 1) * 64 + arow) * A_STRIDE + agrp * 8] = pl.u;
    };
    auto prefetchB = [&](int c, int buf) {
        #pragma unroll
        for (int u = 0; u < 8; u++) {
            int t = tid + u * 256;
            if (t < 1920) {
                int hl = t / 960, idx = t - hl * 960;
                int row = idx >> 2, q = idx & 3;
                const char* src = (const char*)(wslab + (size_t)(hl * 10 + c) * 7680) + row * 64 + q * 16;
                uint32_t dst = sBu + (((buf * 2 + hl) * 240 + row) * B_STRIDE) * 2 + q * 16;
                cpa16(dst, src);
            }
        }
        CP_COMMIT();
    };

    float acc[15][4] = {};

    loadX(0);
    prefetchB(0, 0);
    writeA(0);

    for (int c = 0; c < 10; c++) {
        if (c < 9) { loadX(c + 1); prefetchB(c + 1, (c + 1) & 1); }
        if (c < 9) { CP_WAIT1(); } else { CP_WAIT0(); }
        __syncthreads();
        if (c < 9) writeA((c + 1) & 1);

        const __nv_bfloat16* Ab = As + (c & 1) * 2 * 64 * A_STRIDE;
        const __nv_bfloat16* Bb = Bs + (c & 1) * 2 * 240 * B_STRIDE;

        uint32_t ah[2][4], al[2][4];
        #pragma unroll
        for (int kk = 0; kk < 2; kk++) {
            int r = wm * 16 + grp;
            int k = kk * 16 + tig * 2;
            ah[kk][0] = *(const uint32_t*)&Ab[(0 * 64 + r) * A_STRIDE + k];
            ah[kk][1] = *(const uint32_t*)&Ab[(0 * 64 + r + 8) * A_STRIDE + k];
            ah[kk][2] = *(const uint32_t*)&Ab[(0 * 64 + r) * A_STRIDE + k + 8];
            ah[kk][3] = *(const uint32_t*)&Ab[(0 * 64 + r + 8) * A_STRIDE + k + 8];
            al[kk][0] = *(const uint32_t*)&Ab[(1 * 64 + r) * A_STRIDE + k];
            al[kk][1] = *(const uint32_t*)&Ab[(1 * 64 + r + 8) * A_STRIDE + k];
            al[kk][2] = *(const uint32_t*)&Ab[(1 * 64 + r) * A_STRIDE + k + 8];
            al[kk][3] = *(const uint32_t*)&Ab[(1 * 64 + r + 8) * A_STRIDE + k + 8];
        }
        #pragma unroll
        for (int t8 = 0; t8 < 15; t8++) {
            int br = wn * 120 + t8 * 8 + grp;
            #pragma unroll
            for (int kk = 0; kk < 2; kk++) {
                int k = kk * 16 + tig * 2;
                uint32_t bh0 = *(const uint32_t*)&Bb[(0 * 240 + br) * B_STRIDE + k];
                uint32_t bh1 = *(const uint32_t*)&Bb[(0 * 240 + br) * B_STRIDE + k + 8];
                uint32_t bl0 = *(const uint32_t*)&Bb[(1 * 240 + br) * B_STRIDE + k];
                uint32_t bl1 = *(const uint32_t*)&Bb[(1 * 240 + br) * B_STRIDE + k + 8];
                mma16816(acc[t8], ah[kk], bh0, bh1);
                mma16816(acc[t8], ah[kk], bl0, bl1);
                mma16816(acc[t8], al[kk], bh0, bh1);
            }
        }
        __syncthreads();
    }

    #pragma unroll
    for (int t8 = 0; t8 < 15; t8++) {
        int row = wm * 16 + grp;
        int col = wn * 120 + t8 * 8 + tig * 2;
        Gs[row * 241 + col]           = acc[t8][0];
        Gs[row * 241 + col + 1]       = acc[t8][1];
        Gs[(row + 8) * 241 + col]     = acc[t8][2];
        Gs[(row + 8) * 241 + col + 1] = acc[t8][3];
    }
    __syncthreads();

    for (int e = tid; e < 64 * 240; e += 256) {
        int nl = e >> 6, ml = e & 63;
        int n = nt * 240 + nl;
        if (n < NW) {
            int dd = (n >= G3) ? 1 : 0;
            int q = n - dd * G3;
            float bv = dd ? __ldg(bib + q) : __ldg(bif + n);
            g_xpt[((size_t)(dd * SEGL + l) * G3 + q) * NB + b0 + ml] = Gs[ml * 241 + nl] + bv;
        }
    }
}

// ---------------- persistent GRU recurrence (hT unified h, split barrier) ----------------
__global__ __launch_bounds__(256, 2) void gru_persist(
        const float* __restrict__ bhf, const float* __restrict__ bhb,
        float* __restrict__ out) {
    extern __shared__ char smraw[];
    float* Gs = (float*)smraw;
    uint32_t sb = (uint32_t)__cvta_generic_to_shared(smraw);

    const int bid = blockIdx.x;
    const int d = bid & 1, mt = (bid >> 1) & 31, nt = bid >> 6;
    const int gi = (d * 32 + mt) * 32;
    const int tid = threadIdx.x;
    const int wid = tid >> 5, lane = tid & 31;
    const int wm = wid >> 1, wn = wid & 1;
    const int grp = lane >> 2, tig = lane & 3;
    const int m0 = mt * 64;

    // ldmatrix address components
    const uint32_t aOff = (uint32_t)((lane & 15) * 144 + (wm * 16 + (lane >> 4) * 8) * 2);
    const int hlB = (lane >> 4);
    const int koffB = ((lane >> 3) & 1) * 8;
    const int rowB7 = wn * 120 + (lane & 7);
    const uint32_t bOff = (uint32_t)(((hlB * 240 + rowB7) * 40 + koffB) * 2);

    const __nv_bfloat16* wslab = g_wpk + (size_t)((d * 4 + nt) * 2) * 10 * 7680;
    const float* bh = d ? bhb : bhf;
    const int nvalid = (nt == 3) ? 60 : 80;

    auto prefA = [&](int c, int pp_, int abuf) {
        const char* hhi = (const char*)HT(d, pp_, 0);
        const char* hlo = (const char*)HT(d, pp_, 1);
        int k0 = c * 32;
        #pragma unroll
        for (int u = 0; u < 2; u++) {
            int t = tid + u * 256;
            int hl = t >> 8, idx = t & 255;
            int kr = idx >> 3, q = idx & 7;
            const char* src = (hl ? hlo : hhi) + ((size_t)(k0 + kr) * NB + m0) * 2 + q * 16;
            cpa16(sb + abuf * 9216 + hl * 4608 + kr * 144 + q * 16, src);
        }
    };
    auto prefB = [&](int c, int bbuf) {
        uint32_t bb = sb + (bbuf ? GRU_AB1 : GRU_AB0);
        #pragma unroll
        for (int u = 0; u < 8; u++) {
            int t = tid + u * 256;
            if (t < 1920) {
                int hl = t / 960, idx = t - hl * 960;
                int row = idx >> 2, q = idx & 3;
                const char* src = (const char*)(wslab + (size_t)(hl * 10 + c) * 7680) + row * 64 + q * 16;
                cpa16(bb + ((hl * 240 + row) * 40) * 2 + q * 16, src);
            }
        }
    };

    // prologue: B0 -> buf1, A0 -> abuf0 (pp=0)
    prefB(0, 1); CP_COMMIT();
    prefA(0, 0, 0); CP_COMMIT();

    for (int s = 0; s < SEGL; s++) {
        const int l = d ? (SEGL - 1 - s) : s;
        const int pp = s & 1;

        float acc[15][4] = {};

        for (int c = 0; c < 10; c++) {
            if (c < 9) {
                prefA(c + 1, pp, (c + 1) & 1);
                prefB(c + 1, 1 - ((c + 1) & 1));
                CP_COMMIT();
            }
            if (c < 9) { CP_WAIT1(); } else { CP_WAIT0(); }
            __syncthreads();

            const uint32_t aB = sb + (c & 1) * 9216;
            const uint32_t bB = sb + ((c & 1) ? GRU_AB0 : GRU_AB1) + bOff;

            uint32_t ah[2][4], al[2][4];
            #pragma unroll
            for (int kk = 0; kk < 2; kk++) {
                uint32_t f0, f1, f2, f3;
                ldsm4t(f0, f1, f2, f3, aB + 0 * 4608 + kk * 2304 + aOff);
                ah[kk][0] = f0; ah[kk][1] = f2; ah[kk][2] = f1; ah[kk][3] = f3;
                ldsm4t(f0, f1, f2, f3, aB + 1 * 4608 + kk * 2304 + aOff);
                al[kk][0] = f0; al[kk][1] = f2; al[kk][2] = f1; al[kk][3] = f3;
            }
            #pragma unroll
            for (int t8 = 0; t8 < 15; t8++) {
                uint32_t bb = bB + (uint32_t)(t8 * 640);
                #pragma unroll
                for (int kk = 0; kk < 2; kk++) {
                    uint32_t bh0, bh1, bl0, bl1;
                    ldsm4(bh0, bh1, bl0, bl1, bb + kk * 32);
                    mma16816(acc[t8], ah[kk], bh0, bh1);
                    mma16816(acc[t8], ah[kk], bl0, bl1);
                    mma16816(acc[t8], al[kk], bh0, bh1);
                }
            }
            __syncthreads();
        }

        // next step's B chunk0 -> buf1 (disjoint from Gs overlay); barrier-independent
        if (s < SEGL - 1) { prefB(0, 1); CP_COMMIT(); }

        // ---- stage G ----
        #pragma unroll
        for (int t8 = 0; t8 < 15; t8++) {
            int row = wm * 16 + grp;
            int col = wn * 120 + t8 * 8 + tig * 2;
            Gs[row * 241 + col]           = acc[t8][0];
            Gs[row * 241 + col + 1]       = acc[t8][1];
            Gs[(row + 8) * 241 + col]     = acc[t8][2];
            Gs[(row + 8) * 241 + col + 1] = acc[t8][3];
        }
        __syncthreads();

        // ---- fused gate epilogue: write hT (peer-critical) first ----
        const float* xd = g_xpt + (size_t)(d * SEGL + l) * G3 * NB;
        const __nv_bfloat16* hin_hi = HT(d, pp, 0);
        const __nv_bfloat16* hin_lo = HT(d, pp, 1);
        __nv_bfloat16* hout_hi = HT(d, pp ^ 1, 0);
        __nv_bfloat16* hout_lo = HT(d, pp ^ 1, 1);

        for (int e = tid; e < 64 * 80; e += 256) {
            int ml = e & 63, hcl = e >> 6;
            if (hcl < nvalid) {
                int m = m0 + ml;
                int hc = nt * 80 + hcl;
                size_t hoff = (size_t)hc * NB + m;
                float hr = Gs[ml * 241 + hcl]       + __ldg(bh + hc);
                float hz = Gs[ml * 241 + 80 + hcl]  + __ldg(bh + H + hc);
                float hn = Gs[ml * 241 + 160 + hcl] + __ldg(bh + 2 * H + hc);
                float xr = xd[(size_t)hc * NB + m];
                float xz = xd[(size_t)(H + hc) * NB + m];
                float xn = xd[(size_t)(2 * H + hc) * NB + m];
                float r  = sigmoidf(xr + hr);
                float z  = sigmoidf(xz + hz);
                float nv = tanhf(xn + r * hn);
                float hp = __bfloat162float(hin_hi[hoff]) + __bfloat162float(hin_lo[hoff]);
                float hnew = (1.0f - z) * nv + z * hp;
                __nv_bfloat16 hi = __float2bfloat16(hnew);
                hout_hi[hoff] = hi;
                hout_lo[hoff] = __float2bfloat16(hnew - __bfloat162float(hi));
                Gs[ml * 241 + hcl] = hnew;
            }
        }
        __threadfence();
        __syncthreads();

        // ---- arrive early (peers only need hT) ----
        unsigned myph = 0u;
        bool released = true;
        if (s < SEGL - 1 && tid == 0) {
            myph = atomicAdd(&g_gph[gi], 0u);
            unsigned old = atomicAdd(&g_gcnt[gi], 1u);
            if (old == 3u) {
                atomicExch(&g_gcnt[gi], 0u);
                __threadfence();
                atomicAdd(&g_gph[gi], 1u);
            } else {
                released = false;
            }
        }

        // ---- out write (not peer-critical) overlaps peers' arrival ----
        {
            const int nq = (nt == 3) ? 15 : 20;
            for (int e = tid; e < 64 * nq; e += 256) {
                int ml = e / nq, q = e - ml * nq;
                int m = m0 + ml;
                float4 v = make_float4(Gs[ml * 241 + q * 4],     Gs[ml * 241 + q * 4 + 1],
                                       Gs[ml * 241 + q * 4 + 2], Gs[ml * 241 + q * 4 + 3]);
                *(float4*)(out + ((size_t)m * SEGL + l) * (2 * H) + (size_t)d * H + nt * 80 + q * 4) = v;
            }
        }

        if (s < SEGL - 1) {
            if (tid == 0 && !released) {
                while (atomicAdd(&g_gph[gi], 0u) == myph) __nanosleep(32);
            }
            __syncthreads();
            // post-barrier: only A chunk0 (16KB, L2) on the critical path
            prefA(0, pp ^ 1, 0); CP_COMMIT();
        }
    }
}

// ---------------- launch ----------------
extern "C" void kernel_launch(void* const* d_in, const int* in_sizes, int n_in,
                              void* d_out, int out_size) {
    const float* x      = (const float*)d_in[0];
    const float* bias   = (const float*)d_in[4];
    const float* w_ih_f = (const float*)d_in[5];
    const float* w_hh_f = (const float*)d_in[6];
    const float* b_ih_f = (const float*)d_in[7];
    const float* b_hh_f = (const float*)d_in[8];
    const float* w_ih_b = (const float*)d_in[9];
    const float* w_hh_b = (const float*)d_in[10];
    const float* b_ih_b = (const float*)d_in[11];
    const float* b_hh_b = (const float*)d_in[12];
    float* out = (float*)d_out;

    cudaFuncSetAttribute(gru_persist, cudaFuncAttributeMaxDynamicSharedMemorySize, SMEM_GRU);
    cudaFuncSetAttribute(xproj_mma,   cudaFuncAttributeMaxDynamicSharedMemorySize, SMEM_X);

    setup_h0<<<NB, 128>>>(x);
    prep_whh<<<dim3(10, 4, 2), 256>>>(w_hh_f, w_hh_b);
    prep_wih<<<dim3(10, 8), 256>>>(w_ih_f, w_ih_b);

    xproj_mma<<<dim3(8, 32, SEGL), 256, SMEM_X>>>(x, bias, b_ih_f, b_ih_b);

    gru_persist<<<256, 256, SMEM_GRU>>>(b_hh_f, b_hh_b, out);
}

// round 15
// speedup vs baseline: 1.0734x; 1.0734x over previous
#include <cuda_runtime.h>
#include <cuda_bf16.h>
#include <math.h>
#include <stdint.h>

#define H    300
#define G3   900
#define NB   2048
#define SEGL 48
#define NW   1800
#define KP   320   // K padded: 10 chunks of 32

#define A_STRIDE 40
#define B_STRIDE 40
// As [2buf][2hl][64][40] bf16 = 20480B, Bs at +20480: [2buf][2hl][240][40] bf16 = 76800B
#define SMEM_BYTES 97280

// ---------------- device scratch (zero-initialized at module load) ----------------
__device__ float g_xpt[(size_t)2 * SEGL * G3 * NB];                // [d][l][n=g*300+hc][m]
__device__ float g_hf[(size_t)2 * 2 * KP * NB];                    // [d][pp][k][m] fp32
__device__ __nv_bfloat16 g_hb[(size_t)2 * 2 * 2 * NB * KP];        // [d][pp][hl][m][KP]
__device__ __nv_bfloat16 g_wpk[(size_t)2 * 4 * 2 * 10 * 7680];     // W_hh slabs
__device__ __nv_bfloat16 g_wih_pk[(size_t)8 * 2 * 10 * 7680];      // W_ih slabs (N padded 1920)
__device__ unsigned g_gcnt[64 * 32];                               // group barriers (128B slots)
__device__ unsigned g_gph[64 * 32];

__device__ __forceinline__ __nv_bfloat16* HB(int d, int pp, int hl) {
    return g_hb + ((size_t)(((d * 2 + pp) * 2) + hl)) * NB * KP;
}

// fast activations: MUFU-based, overflow-safe
__device__ __forceinline__ float fast_sigmoid(float v) {
    return __fdividef(1.0f, 1.0f + __expf(-v));
}
__device__ __forceinline__ float fast_tanh(float v) {
    float av = fabsf(v);
    float t  = __expf(-2.0f * av);              // ->0 on overflow, safe
    float r  = __fdividef(1.0f - t, 1.0f + t);
    return copysignf(r, v);
}

__device__ __forceinline__ void mma16816(float* c, const uint32_t* a, uint32_t b0, uint32_t b1) {
    asm volatile("mma.sync.aligned.m16n8k16.row.col.f32.bf16.bf16.f32 "
        "{%0,%1,%2,%3}, {%4,%5,%6,%7}, {%8,%9}, {%0,%1,%2,%3};"
        : "+f"(c[0]), "+f"(c[1]), "+f"(c[2]), "+f"(c[3])
        : "r"(a[0]), "r"(a[1]), "r"(a[2]), "r"(a[3]), "r"(b0), "r"(b1));
}
__device__ __forceinline__ void ldsm4(uint32_t& a, uint32_t& b, uint32_t& c, uint32_t& d, uint32_t addr) {
    asm volatile("ldmatrix.sync.aligned.m8n8.x4.shared.b16 {%0,%1,%2,%3}, [%4];"
        : "=r"(a), "=r"(b), "=r"(c), "=r"(d) : "r"(addr));
}
__device__ __forceinline__ void cpa16(uint32_t dst, const void* src) {
    asm volatile("cp.async.cg.shared.global [%0], [%1], 16;" :: "r"(dst), "l"(src));
}
#define CP_COMMIT() asm volatile("cp.async.commit_group;")
#define CP_WAIT1()  asm volatile("cp.async.wait_group 1;")
#define CP_WAIT0()  asm volatile("cp.async.wait_group 0;")

__device__ __forceinline__ unsigned ld_relaxed(const unsigned* p) {
    unsigned v;
    asm volatile("ld.relaxed.gpu.u32 %0, [%1];" : "=r"(v) : "l"(p) : "memory");
    return v;
}

// ---------------- setup: h0 = segment max -> hf (transposed) + hb hi/lo ----------------
__global__ void setup_h0(const float* __restrict__ x) {
    int b = blockIdx.x;
    const float* xb = x + (size_t)b * SEGL * H;
    for (int h = threadIdx.x; h < H; h += blockDim.x) {
        float mx = -INFINITY;
        #pragma unroll 4
        for (int l = 0; l < SEGL; l++) mx = fmaxf(mx, xb[(size_t)l * H + h]);
        __nv_bfloat16 hi = __float2bfloat16(mx);
        __nv_bfloat16 lo = __float2bfloat16(mx - __bfloat162float(hi));
        for (int d = 0; d < 2; d++) {
            g_hf[((size_t)(d * 2 + 0) * KP + h) * NB + b] = mx;
            HB(d, 0, 0)[(size_t)b * KP + h] = hi;
            HB(d, 0, 1)[(size_t)b * KP + h] = lo;
        }
    }
}

// ---------------- prep: W_hh -> gate-blocked hi/lo k32 slabs ----------------
__global__ void prep_whh(const float* __restrict__ whf, const float* __restrict__ whb) {
    int c = blockIdx.x, nt = blockIdx.y, d = blockIdx.z;
    const float* w = d ? whb : whf;
    __nv_bfloat16* hi_base = g_wpk + (size_t)(((d * 4 + nt) * 2 + 0) * 10 + c) * 7680;
    __nv_bfloat16* lo_base = g_wpk + (size_t)(((d * 4 + nt) * 2 + 1) * 10 + c) * 7680;
    for (int e = threadIdx.x; e < 7680; e += blockDim.x) {
        int row = e >> 5, col = e & 31;
        int g = row / 80, hcl = row % 80;
        int hc = nt * 80 + hcl;
        int k = c * 32 + col;
        float v = (hc < H && k < H) ? w[(size_t)(g * H + hc) * H + k] : 0.0f;
        __nv_bfloat16 hi = __float2bfloat16(v);
        __nv_bfloat16 lo = __float2bfloat16(v - __bfloat162float(hi));
        hi_base[e] = hi;
        lo_base[e] = lo;
    }
}

// ---------------- prep: W_ih -> hi/lo k32 slabs, N padded to 1920 ----------------
__global__ void prep_wih(const float* __restrict__ wif, const float* __restrict__ wib) {
    int c = blockIdx.x, nt = blockIdx.y;
    __nv_bfloat16* hi_base = g_wih_pk + (size_t)((nt * 2 + 0) * 10 + c) * 7680;
    __nv_bfloat16* lo_base = g_wih_pk + (size_t)((nt * 2 + 1) * 10 + c) * 7680;
    for (int e = threadIdx.x; e < 7680; e += blockDim.x) {
        int row = e >> 5, col = e & 31;
        int n = nt * 240 + row;
        int k = c * 32 + col;
        float v = 0.0f;
        if (k < H) {
            if (n < G3)      v = wif[(size_t)n * H + k];
            else if (n < NW) v = wib[(size_t)(n - G3) * H + k];
        }
        __nv_bfloat16 hi = __float2bfloat16(v);
        __nv_bfloat16 lo = __float2bfloat16(v - __bfloat162float(hi));
        hi_base[e] = hi;
        lo_base[e] = lo;
    }
}

// ---------------- xproj MMA (scalar frag loads, 2 CTAs/SM pinned) ----------------
__global__ __launch_bounds__(256, 2) void xproj_mma(
        const float* __restrict__ x, const float* __restrict__ bias,
        const float* __restrict__ bif, const float* __restrict__ bib) {
    extern __shared__ char smraw[];
    __nv_bfloat16* As = (__nv_bfloat16*)smraw;
    __nv_bfloat16* Bs = (__nv_bfloat16*)(smraw + 20480);
    float* Gs = (float*)smraw;
    uint32_t sBu = (uint32_t)__cvta_generic_to_shared(Bs);

    const int nt = blockIdx.x, mt = blockIdx.y, l = blockIdx.z;
    const int b0 = mt * 64;
    const int tid = threadIdx.x;
    const int wid = tid >> 5, lane = tid & 31;
    const int wm = wid >> 1, wn = wid & 1;
    const int grp = lane >> 2, tig = lane & 3;

    const __nv_bfloat16* wslab = g_wih_pk + (size_t)(nt * 2) * 10 * 7680;

    const int arow = tid >> 2, agrp = tid & 3;
    const size_t xbase = ((size_t)(b0 + arow) * SEGL + l) * H;
    float4 xv0, xv1;

    auto loadX = [&](int c) {
        int k = c * 32 + agrp * 8;
        xv0 = make_float4(0.f, 0.f, 0.f, 0.f);
        xv1 = make_float4(0.f, 0.f, 0.f, 0.f);
        if (k < H) {
            float4 v = *(const float4*)(x + xbase + k);
            float4 bv = *(const float4*)(bias + k);
            xv0 = make_float4(fmaxf(v.x + bv.x, 0.f), fmaxf(v.y + bv.y, 0.f),
                              fmaxf(v.z + bv.z, 0.f), fmaxf(v.w + bv.w, 0.f));
        }
        if (k + 4 < H) {
            float4 v = *(const float4*)(x + xbase + k + 4);
            float4 bv = *(const float4*)(bias + k + 4);
            xv1 = make_float4(fmaxf(v.x + bv.x, 0.f), fmaxf(v.y + bv.y, 0.f),
                              fmaxf(v.z + bv.z, 0.f), fmaxf(v.w + bv.w, 0.f));
        }
    };
    auto writeA = [&](int buf) {
        float vv[8] = {xv0.x, xv0.y, xv0.z, xv0.w, xv1.x, xv1.y, xv1.z, xv1.w};
        union { __nv_bfloat16 h[8]; uint4 u; } ph, pl;
        #pragma unroll
        for (int i = 0; i < 8; i++) {
            __nv_bfloat16 hi = __float2bfloat16(vv[i]);
            ph.h[i] = hi;
            pl.h[i] = __float2bfloat16(vv[i] - __bfloat162float(hi));
        }
        *(uint4*)&As[((buf * 2 + 0) * 64 + arow) * A_STRIDE + agrp * 8] = ph.u;
        *(uint4*)&As[((buf * 2 + 1) * 64 + arow) * A_STRIDE + agrp * 8] = pl.u;
    };
    auto prefetchB = [&](int c, int buf) {
        #pragma unroll
        for (int u = 0; u < 8; u++) {
            int t = tid + u * 256;
            if (t < 1920) {
                int hl = t / 960, idx = t - hl * 960;
                int row = idx >> 2, q = idx & 3;
                const char* src = (const char*)(wslab + (size_t)(hl * 10 + c) * 7680) + row * 64 + q * 16;
                uint32_t dst = sBu + (((buf * 2 + hl) * 240 + row) * B_STRIDE) * 2 + q * 16;
                cpa16(dst, src);
            }
        }
        CP_COMMIT();
    };

    float acc[15][4] = {};

    loadX(0);
    prefetchB(0, 0);
    writeA(0);

    for (int c = 0; c < 10; c++) {
        if (c < 9) { loadX(c + 1); prefetchB(c + 1, (c + 1) & 1); }
        if (c < 9) { CP_WAIT1(); } else { CP_WAIT0(); }
        __syncthreads();
        if (c < 9) writeA((c + 1) & 1);

        const __nv_bfloat16* Ab = As + (c & 1) * 2 * 64 * A_STRIDE;
        const __nv_bfloat16* Bb = Bs + (c & 1) * 2 * 240 * B_STRIDE;

        uint32_t ah[2][4], al[2][4];
        #pragma unroll
        for (int kk = 0; kk < 2; kk++) {
            int r = wm * 16 + grp;
            int k = kk * 16 + tig * 2;
            ah[kk][0] = *(const uint32_t*)&Ab[(0 * 64 + r) * A_STRIDE + k];
            ah[kk][1] = *(const uint32_t*)&Ab[(0 * 64 + r + 8) * A_STRIDE + k];
            ah[kk][2] = *(const uint32_t*)&Ab[(0 * 64 + r) * A_STRIDE + k + 8];
            ah[kk][3] = *(const uint32_t*)&Ab[(0 * 64 + r + 8) * A_STRIDE + k + 8];
            al[kk][0] = *(const uint32_t*)&Ab[(1 * 64 + r) * A_STRIDE + k];
            al[kk][1] = *(const uint32_t*)&Ab[(1 * 64 + r + 8) * A_STRIDE + k];
            al[kk][2] = *(const uint32_t*)&Ab[(1 * 64 + r) * A_STRIDE + k + 8];
            al[kk][3] = *(const uint32_t*)&Ab[(1 * 64 + r + 8) * A_STRIDE + k + 8];
        }
        #pragma unroll
        for (int t8 = 0; t8 < 15; t8++) {
            int br = wn * 120 + t8 * 8 + grp;
            #pragma unroll
            for (int kk = 0; kk < 2; kk++) {
                int k = kk * 16 + tig * 2;
                uint32_t bh0 = *(const uint32_t*)&Bb[(0 * 240 + br) * B_STRIDE + k];
                uint32_t bh1 = *(const uint32_t*)&Bb[(0 * 240 + br) * B_STRIDE + k + 8];
                uint32_t bl0 = *(const uint32_t*)&Bb[(1 * 240 + br) * B_STRIDE + k];
                uint32_t bl1 = *(const uint32_t*)&Bb[(1 * 240 + br) * B_STRIDE + k + 8];
                mma16816(acc[t8], ah[kk], bh0, bh1);
                mma16816(acc[t8], ah[kk], bl0, bl1);
                mma16816(acc[t8], al[kk], bh0, bh1);
            }
        }
        __syncthreads();
    }

    #pragma unroll
    for (int t8 = 0; t8 < 15; t8++) {
        int row = wm * 16 + grp;
        int col = wn * 120 + t8 * 8 + tig * 2;
        Gs[row * 241 + col]           = acc[t8][0];
        Gs[row * 241 + col + 1]       = acc[t8][1];
        Gs[(row + 8) * 241 + col]     = acc[t8][2];
        Gs[(row + 8) * 241 + col + 1] = acc[t8][3];
    }
    __syncthreads();

    for (int e = tid; e < 64 * 240; e += 256) {
        int nl = e >> 6, ml = e & 63;
        int n = nt * 240 + nl;
        if (n < NW) {
            int dd = (n >= G3) ? 1 : 0;
            int q = n - dd * G3;
            float bv = dd ? __ldg(bib + q) : __ldg(bif + n);
            g_xpt[((size_t)(dd * SEGL + l) * G3 + q) * NB + b0 + ml] = Gs[ml * 241 + nl] + bv;
        }
    }
}

// ---------------- persistent GRU recurrence (ldmatrix, group barriers) ----------------
__global__ __launch_bounds__(256, 2) void gru_persist(
        const float* __restrict__ bhf, const float* __restrict__ bhb,
        float* __restrict__ out) {
    extern __shared__ char smraw[];
    __nv_bfloat16* As = (__nv_bfloat16*)smraw;
    __nv_bfloat16* Bs = (__nv_bfloat16*)(smraw + 20480);
    float* Gs = (float*)smraw;
    uint32_t sAu = (uint32_t)__cvta_generic_to_shared(As);
    uint32_t sBu = (uint32_t)__cvta_generic_to_shared(Bs);

    const int bid = blockIdx.x;
    const int d = bid & 1, mt = (bid >> 1) & 31, nt = bid >> 6;
    const int gi = (d * 32 + mt) * 32;
    const int tid = threadIdx.x;
    const int wid = tid >> 5, lane = tid & 31;
    const int wm = wid >> 1, wn = wid & 1;
    const int grp = lane >> 2, tig = lane & 3;
    const int m0 = mt * 64;

    const int rowA = wm * 16 + ((lane >> 3) & 1) * 8 + (lane & 7);
    const int koffA = (lane >> 4) * 8;
    const int hlB = (lane >> 4);
    const int koffB = ((lane >> 3) & 1) * 8;
    const int rowB7 = wn * 120 + (lane & 7);

    const __nv_bfloat16* wslab = g_wpk + (size_t)((d * 4 + nt) * 2) * 10 * 7680;
    const float* bh = d ? bhb : bhf;
    const int nvalid = (nt == 3) ? 60 : 80;

    for (int s = 0; s < SEGL; s++) {
        const int l = d ? (SEGL - 1 - s) : s;
        const int pp = s & 1;
        const char* h_hi = (const char*)HB(d, pp, 0) + (size_t)m0 * KP * 2;
        const char* h_lo = (const char*)HB(d, pp, 1) + (size_t)m0 * KP * 2;

        auto prefetch = [&](int c, int buf) {
            int k0 = c * 32;
            #pragma unroll
            for (int u = 0; u < 2; u++) {
                int t = tid + u * 256;
                int row = t >> 3, hl = (t >> 2) & 1, q = t & 3;
                const char* src = (hl ? h_lo : h_hi) + ((size_t)row * KP + k0) * 2 + q * 16;
                uint32_t dst = sAu + (((buf * 2 + hl) * 64 + row) * A_STRIDE) * 2 + q * 16;
                cpa16(dst, src);
            }
            #pragma unroll
            for (int u = 0; u < 8; u++) {
                int t = tid + u * 256;
                if (t < 1920) {
                    int hl = t / 960, idx = t - hl * 960;
                    int row = idx >> 2, q = idx & 3;
                    const char* src = (const char*)(wslab + (size_t)(hl * 10 + c) * 7680) + row * 64 + q * 16;
                    uint32_t dst = sBu + (((buf * 2 + hl) * 240 + row) * B_STRIDE) * 2 + q * 16;
                    cpa16(dst, src);
                }
            }
            CP_COMMIT();
        };

        float acc[15][4] = {};

        prefetch(0, 0);
        for (int c = 0; c < 10; c++) {
            if (c < 9) prefetch(c + 1, (c + 1) & 1);
            if (c < 9) { CP_WAIT1(); } else { CP_WAIT0(); }
            __syncthreads();

            const int buf = c & 1;
            uint32_t aBase = sAu + ((uint32_t)(buf * 2) * 64 * A_STRIDE + rowA * A_STRIDE + koffA) * 2;
            uint32_t bBase = sBu + ((uint32_t)(buf * 480 + hlB * 240 + rowB7) * B_STRIDE + koffB) * 2;

            uint32_t ah[2][4], al[2][4];
            #pragma unroll
            for (int kk = 0; kk < 2; kk++) {
                ldsm4(ah[kk][0], ah[kk][1], ah[kk][2], ah[kk][3], aBase + kk * 32);
                ldsm4(al[kk][0], al[kk][1], al[kk][2], al[kk][3], aBase + (64u * A_STRIDE) * 2 + kk * 32);
            }
            #pragma unroll
            for (int t8 = 0; t8 < 15; t8++) {
                uint32_t bb = bBase + (uint32_t)(t8 * 8 * B_STRIDE) * 2;
                #pragma unroll
                for (int kk = 0; kk < 2; kk++) {
                    uint32_t bh0, bh1, bl0, bl1;
                    ldsm4(bh0, bh1, bl0, bl1, bb + kk * 32);
                    mma16816(acc[t8], ah[kk], bh0, bh1);
                    mma16816(acc[t8], ah[kk], bl0, bl1);
                    mma16816(acc[t8], al[kk], bh0, bh1);
                }
            }
            __syncthreads();
        }

        // ---- stage G ----
        #pragma unroll
        for (int t8 = 0; t8 < 15; t8++) {
            int row = wm * 16 + grp;
            int col = wn * 120 + t8 * 8 + tig * 2;
            Gs[row * 241 + col]           = acc[t8][0];
            Gs[row * 241 + col + 1]       = acc[t8][1];
            Gs[(row + 8) * 241 + col]     = acc[t8][2];
            Gs[(row + 8) * 241 + col + 1] = acc[t8][3];
        }
        __syncthreads();

        // ---- fused gate epilogue (fast activations) ----
        const float* xd   = g_xpt + (size_t)(d * SEGL + l) * G3 * NB;
        const float* hfin = g_hf + (size_t)(d * 2 + pp) * KP * NB;
        float*      hfout = g_hf + (size_t)(d * 2 + (pp ^ 1)) * KP * NB;

        for (int e = tid; e < 64 * 80; e += 256) {
            int ml = e & 63, hcl = e >> 6;
            if (hcl < nvalid) {
                int m = m0 + ml;
                int hc = nt * 80 + hcl;
                float hr = Gs[ml * 241 + hcl]        + __ldg(bh + hc);
                float hz = Gs[ml * 241 + 80 + hcl]   + __ldg(bh + H + hc);
                float hn = Gs[ml * 241 + 160 + hcl]  + __ldg(bh + 2 * H + hc);
                float xr = xd[(size_t)hc * NB + m];
                float xz = xd[(size_t)(H + hc) * NB + m];
                float xn = xd[(size_t)(2 * H + hc) * NB + m];
                float r  = fast_sigmoid(xr + hr);
                float z  = fast_sigmoid(xz + hz);
                float nv = fast_tanh(xn + r * hn);
                float hp = hfin[(size_t)hc * NB + m];
                float hnew = (1.0f - z) * nv + z * hp;
                hfout[(size_t)hc * NB + m] = hnew;
                __nv_bfloat16 hi = __float2bfloat16(hnew);
                __nv_bfloat16 lo = __float2bfloat16(hnew - __bfloat162float(hi));
                uint32_t packed = (uint32_t)*(uint16_t*)&hi | ((uint32_t)*(uint16_t*)&lo << 16);
                Gs[ml * 241 + hcl] = hnew;
                Gs[ml * 241 + 80 + hcl] = __uint_as_float(packed);
            }
        }
        __syncthreads();

        // coalesced out write
        {
            const int nq = (nt == 3) ? 15 : 20;
            for (int e = tid; e < 64 * nq; e += 256) {
                int ml = e / nq, q = e - ml * nq;
                int m = m0 + ml;
                float4 v = make_float4(Gs[ml * 241 + q * 4],     Gs[ml * 241 + q * 4 + 1],
                                       Gs[ml * 241 + q * 4 + 2], Gs[ml * 241 + q * 4 + 3]);
                *(float4*)(out + ((size_t)m * SEGL + l) * (2 * H) + (size_t)d * H + nt * 80 + q * 4) = v;
            }
        }
        // coalesced packed bf16 h write
        {
            __nv_bfloat16* ho_hi = HB(d, pp ^ 1, 0);
            __nv_bfloat16* ho_lo = HB(d, pp ^ 1, 1);
            const int nj = (nt == 3) ? 30 : 40;
            for (int e = tid; e < 64 * nj; e += 256) {
                int ml = e / nj, j = e - ml * nj;
                int m = m0 + ml;
                uint32_t p0 = __float_as_uint(Gs[ml * 241 + 80 + 2 * j]);
                uint32_t p1 = __float_as_uint(Gs[ml * 241 + 80 + 2 * j + 1]);
                uint32_t hiw = (p0 & 0xFFFFu) | (p1 << 16);
                uint32_t low = (p0 >> 16) | (p1 & 0xFFFF0000u);
                size_t off = ((size_t)m * KP + nt * 80 + 2 * j);
                *(uint32_t*)((char*)ho_hi + off * 2) = hiw;
                *(uint32_t*)((char*)ho_lo + off * 2) = low;
            }
        }

        // ---- 4-CTA group barrier (cheap relaxed polling) ----
        if (s < SEGL - 1) {
            __threadfence();
            __syncthreads();
            if (tid == 0) {
                unsigned myph = ld_relaxed(&g_gph[gi]);
                unsigned old  = atomicAdd(&g_gcnt[gi], 1u);
                if (old == 3u) {
                    atomicExch(&g_gcnt[gi], 0u);
                    __threadfence();
                    atomicAdd(&g_gph[gi], 1u);
                } else {
                    while (ld_relaxed(&g_gph[gi]) == myph) __nanosleep(32);
                }
                __threadfence();
            }
            __syncthreads();
        }
    }
}

// ---------------- launch ----------------
extern "C" void kernel_launch(void* const* d_in, const int* in_sizes, int n_in,
                              void* d_out, int out_size) {
    const float* x      = (const float*)d_in[0];
    const float* bias   = (const float*)d_in[4];
    const float* w_ih_f = (const float*)d_in[5];
    const float* w_hh_f = (const float*)d_in[6];
    const float* b_ih_f = (const float*)d_in[7];
    const float* b_hh_f = (const float*)d_in[8];
    const float* w_ih_b = (const float*)d_in[9];
    const float* w_hh_b = (const float*)d_in[10];
    const float* b_ih_b = (const float*)d_in[11];
    const float* b_hh_b = (const float*)d_in[12];
    float* out = (float*)d_out;

    cudaFuncSetAttribute(gru_persist, cudaFuncAttributeMaxDynamicSharedMemorySize, SMEM_BYTES);
    cudaFuncSetAttribute(xproj_mma,   cudaFuncAttributeMaxDynamicSharedMemorySize, SMEM_BYTES);

    setup_h0<<<NB, 128>>>(x);
    prep_whh<<<dim3(10, 4, 2), 256>>>(w_hh_f, w_hh_b);
    prep_wih<<<dim3(10, 8), 256>>>(w_ih_f, w_ih_b);

    xproj_mma<<<dim3(8, 32, SEGL), 256, SMEM_BYTES>>>(x, bias, b_ih_f, b_ih_b);

    gru_persist<<<256, 256, SMEM_BYTES>>>(b_hh_f, b_hh_b, out);
}